// round 14
// baseline (speedup 1.0000x reference)
#include <cuda_runtime.h>
#include <cstdint>

// FasterTensorProduct, factored form:
//   out[b,n1,n2,o] = sum_{s=0..3} sh[b,n1,s] * P[b,n2,s,o]
// where P[b,n2,s,:] = y(x_{b,n2}, e_s) is the bilinear map on the 4 sh basis
// vectors.
//
// Kernel A (ftp_precompute4): 128 blocks x 272 threads; each block computes P
// for 4 consecutive n2 rows with 4x weight-load reuse. (unchanged, proven)
// Kernel B (ftp_fanout_tma): computes 32x272 output tiles in smem, then issues
// TMA bulk stores (cp.async.bulk shared::cta -> global) — removes the
// 12-cyc/STG.128 LSU issue serialization that froze the STG version at 13.5us.
//
// Dims: M0E=64, M1O=32, M1E=32, M0O=16, IN_DIM=OUT_DIM=272, B=4, N=128.
// Weights (flat, row-major, each block scaled by 1/sqrt(rows)):
//   W0e at 0     : (96,64)
//   W1o at 6144  : (128,32)
//   W1e at 10240 : (80,32)
//   W0o at 12800 : (48,16)

#define B_DIM 4
#define N_DIM 128
#define IO_DIM 272
#define W_NUMEL 13568
#define ROWS_PER_BLK 32

__device__ float4 g_Pbuf[B_DIM * N_DIM * IO_DIM];   // [b][n2][o] -> (P_s0..P_s3)

// ---------------------------------------------------------------------------
// Kernel A: compute P, 4 rows per block with 4x weight-load reuse
// grid = (32, 4), block = 272
// ---------------------------------------------------------------------------
__global__ __launch_bounds__(272) void ftp_precompute4(
    const float* __restrict__ in_, const float* __restrict__ w)
{
    __shared__ float xs[4 * IO_DIM];   // xs[r*272 + k]

    const int tid    = threadIdx.x;
    const int n2base = blockIdx.x * 4;
    const int b      = blockIdx.y;

    // 4 consecutive input rows are contiguous: 1088 floats = 272 float4
    {
        const float4* src = reinterpret_cast<const float4*>(
            in_ + (size_t)(b * N_DIM + n2base) * IO_DIM);
        reinterpret_cast<float4*>(xs)[tid] = src[tid];
    }
    __syncthreads();

    const float inv2 = 0.7071067811865476f;   // 1/sqrt(2)
    const float inv3 = 0.5773502691896258f;   // 1/sqrt(3)

    float p0[4], p1[4], p2[4], p3[4];
    const int o = tid;

    if (o < 64) {
        // y0e: out0e = [x0e*sh0, (x1o . sh1)/sqrt3], W0e (96,64), 1/sqrt(96)
        const float s = 0.10206207261596575f;
        float a0[4] = {0.f,0.f,0.f,0.f};
        float a1[4] = {0.f,0.f,0.f,0.f};
        float a2[4] = {0.f,0.f,0.f,0.f};
        float a3[4] = {0.f,0.f,0.f,0.f};
        #pragma unroll
        for (int k = 0; k < 64; k++) {
            float wv = w[k * 64 + o];
            #pragma unroll
            for (int r = 0; r < 4; r++) a0[r] += xs[r * IO_DIM + k] * wv;
        }
        #pragma unroll
        for (int m = 0; m < 32; m++) {
            float wv = w[(64 + m) * 64 + o];
            #pragma unroll
            for (int r = 0; r < 4; r++) {
                a1[r] += xs[r * IO_DIM + 64 + 3 * m + 0] * wv;
                a2[r] += xs[r * IO_DIM + 64 + 3 * m + 1] * wv;
                a3[r] += xs[r * IO_DIM + 64 + 3 * m + 2] * wv;
            }
        }
        #pragma unroll
        for (int r = 0; r < 4; r++) {
            p0[r] = a0[r] * s;
            p1[r] = a1[r] * (s * inv3);
            p2[r] = a2[r] * (s * inv3);
            p3[r] = a3[r] * (s * inv3);
        }
    } else if (o < 160) {
        // y1o: o = 64 + oo*3 + cp. W1o (128,32) at 6144, 1/sqrt(128)
        // rows: [0:64) x0e*sh1[c], [64:96) x1o*sh0, [96:128) cross(x1e,sh1)/sqrt2
        const float s  = 0.08838834764831845f;
        const int  t  = o - 64;
        const int  oo = t / 3;
        const int  cp = t - 3 * oo;
        const int  ca = (cp + 1) % 3;
        const int  cb = (cp + 2) % 3;
        const float* w1 = w + 6144;
        float A[4]  = {0.f,0.f,0.f,0.f};
        float Bc[4] = {0.f,0.f,0.f,0.f};
        float Ca[4] = {0.f,0.f,0.f,0.f};
        float Cb[4] = {0.f,0.f,0.f,0.f};
        #pragma unroll
        for (int k = 0; k < 64; k++) {
            float wv = w1[k * 32 + oo];
            #pragma unroll
            for (int r = 0; r < 4; r++) Bc[r] += xs[r * IO_DIM + k] * wv;
        }
        #pragma unroll
        for (int m = 0; m < 32; m++) {
            float wva = w1[(64 + m) * 32 + oo];
            float wvb = w1[(96 + m) * 32 + oo];
            #pragma unroll
            for (int r = 0; r < 4; r++) {
                A[r]  += xs[r * IO_DIM + 64 + 3 * m + cp] * wva;
                Ca[r] += xs[r * IO_DIM + 160 + 3 * m + cb] * wvb;  // cross(x1e,e_ca)[cp] = -x1e[cb]
                Cb[r] += xs[r * IO_DIM + 160 + 3 * m + ca] * wvb;  // cross(x1e,e_cb)[cp] = +x1e[ca]
            }
        }
        #pragma unroll
        for (int r = 0; r < 4; r++) {
            p0[r] = A[r] * s;
            float vB = Bc[r] * s;
            float vA = -Ca[r] * (s * inv2);
            float vC =  Cb[r] * (s * inv2);
            p1[r] = (cp == 0) ? vB : ((ca == 0) ? vA : vC);
            p2[r] = (cp == 1) ? vB : ((ca == 1) ? vA : vC);
            p3[r] = (cp == 2) ? vB : ((ca == 2) ? vA : vC);
        }
    } else if (o < 256) {
        // y1e: o = 160 + oo*3 + cp. W1e (80,32) at 10240, 1/sqrt(80)
        // rows: [0:32) cross(x1o,sh1)/sqrt2, [32:64) x1e*sh0, [64:80) x0o*sh1[c]
        const float s  = 0.11180339887498949f;
        const int  t  = o - 160;
        const int  oo = t / 3;
        const int  cp = t - 3 * oo;
        const int  ca = (cp + 1) % 3;
        const int  cb = (cp + 2) % 3;
        const float* w2 = w + 10240;
        float A[4]  = {0.f,0.f,0.f,0.f};
        float Bc[4] = {0.f,0.f,0.f,0.f};
        float Ca[4] = {0.f,0.f,0.f,0.f};
        float Cb[4] = {0.f,0.f,0.f,0.f};
        #pragma unroll
        for (int m = 0; m < 32; m++) {
            float wva = w2[(32 + m) * 32 + oo];
            float wvb = w2[m * 32 + oo];
            #pragma unroll
            for (int r = 0; r < 4; r++) {
                A[r]  += xs[r * IO_DIM + 160 + 3 * m + cp] * wva;
                Ca[r] += xs[r * IO_DIM + 64 + 3 * m + cb] * wvb;
                Cb[r] += xs[r * IO_DIM + 64 + 3 * m + ca] * wvb;
            }
        }
        #pragma unroll
        for (int k = 0; k < 16; k++) {
            float wv = w2[(64 + k) * 32 + oo];
            #pragma unroll
            for (int r = 0; r < 4; r++) Bc[r] += xs[r * IO_DIM + 256 + k] * wv;
        }
        #pragma unroll
        for (int r = 0; r < 4; r++) {
            p0[r] = A[r] * s;
            float vB = Bc[r] * s;
            float vA = -Ca[r] * (s * inv2);
            float vC =  Cb[r] * (s * inv2);
            p1[r] = (cp == 0) ? vB : ((ca == 0) ? vA : vC);
            p2[r] = (cp == 1) ? vB : ((ca == 1) ? vA : vC);
            p3[r] = (cp == 2) ? vB : ((ca == 2) ? vA : vC);
        }
    } else {
        // y0o: o = 256 + oy. W0o (48,16) at 12800, 1/sqrt(48)
        const float s  = 0.14433756729740645f;
        const int  oy = o - 256;
        const float* w3 = w + 12800;
        float a0[4] = {0.f,0.f,0.f,0.f};
        float a1[4] = {0.f,0.f,0.f,0.f};
        float a2[4] = {0.f,0.f,0.f,0.f};
        float a3[4] = {0.f,0.f,0.f,0.f};
        #pragma unroll
        for (int k = 0; k < 16; k++) {
            float wv = w3[(32 + k) * 16 + oy];
            #pragma unroll
            for (int r = 0; r < 4; r++) a0[r] += xs[r * IO_DIM + 256 + k] * wv;
        }
        #pragma unroll
        for (int m = 0; m < 32; m++) {
            float wv = w3[m * 16 + oy];
            #pragma unroll
            for (int r = 0; r < 4; r++) {
                a1[r] += xs[r * IO_DIM + 160 + 3 * m + 0] * wv;
                a2[r] += xs[r * IO_DIM + 160 + 3 * m + 1] * wv;
                a3[r] += xs[r * IO_DIM + 160 + 3 * m + 2] * wv;
            }
        }
        #pragma unroll
        for (int r = 0; r < 4; r++) {
            p0[r] = a0[r] * s;
            p1[r] = a1[r] * (s * inv3);
            p2[r] = a2[r] * (s * inv3);
            p3[r] = a3[r] * (s * inv3);
        }
    }

    #pragma unroll
    for (int r = 0; r < 4; r++)
        g_Pbuf[(b * N_DIM + n2base + r) * IO_DIM + o] =
            make_float4(p0[r], p1[r], p2[r], p3[r]);
}

// ---------------------------------------------------------------------------
// Kernel B: fan-out via smem tile + TMA bulk store.
// grid = (n2=128, b=4, quarter=4); block = 272 threads.
// Tile: 32 n1-rows x 272 floats (34,816 B). Each (b,n1,n2) output row is a
// contiguous, 16B-aligned 1088 B segment -> one cp.async.bulk per row,
// issued by threads 0..31.
// ---------------------------------------------------------------------------
__global__ __launch_bounds__(272) void ftp_fanout_tma(
    const float4* __restrict__ sh4, float* __restrict__ out)
{
    __shared__ __align__(16) float tile[ROWS_PER_BLK * IO_DIM];
    __shared__ float4 shs[ROWS_PER_BLK];

    const int tid = threadIdx.x;
    const int n2  = blockIdx.x;
    const int b   = blockIdx.y;
    const int qtr = blockIdx.z;

    if (tid < ROWS_PER_BLK)
        shs[tid] = sh4[b * N_DIM + qtr * ROWS_PER_BLK + tid];

    const int o4 = tid % 68;   // float4 column within the 272-wide row
    const int g  = tid / 68;   // 0..3

    const float4* __restrict__ Prow =
        g_Pbuf + (b * N_DIM + n2) * IO_DIM + o4 * 4;
    const float4 q0 = Prow[0];
    const float4 q1 = Prow[1];
    const float4 q2 = Prow[2];
    const float4 q3 = Prow[3];

    __syncthreads();

    #pragma unroll
    for (int i = 0; i < 8; i++) {
        const int j = g + 4 * i;           // n1-local row 0..31
        float4 s4 = shs[j];
        float4 r;
        r.x = q0.x * s4.x + q0.y * s4.y + q0.z * s4.z + q0.w * s4.w;
        r.y = q1.x * s4.x + q1.y * s4.y + q1.z * s4.z + q1.w * s4.w;
        r.z = q2.x * s4.x + q2.y * s4.y + q2.z * s4.z + q2.w * s4.w;
        r.w = q3.x * s4.x + q3.y * s4.y + q3.z * s4.z + q3.w * s4.w;
        *reinterpret_cast<float4*>(&tile[j * IO_DIM + o4 * 4]) = r;
    }

    __syncthreads();

    // One bulk store per n1-row, issued by threads 0..31.
    if (tid < ROWS_PER_BLK) {
        // make generic-proxy smem writes visible to the async proxy
        asm volatile("fence.proxy.async.shared::cta;" ::: "memory");

        const int n1 = qtr * ROWS_PER_BLK + tid;
        float* dst = out + ((size_t)(b * N_DIM + n1) * N_DIM + n2) * IO_DIM;
        const float* src = &tile[tid * IO_DIM];
        uint32_t saddr;
        asm("{ .reg .u64 t; cvta.to.shared.u64 t, %1; cvt.u32.u64 %0, t; }"
            : "=r"(saddr) : "l"(src));

        asm volatile(
            "cp.async.bulk.global.shared::cta.bulk_group [%0], [%1], %2;"
            :: "l"(dst), "r"(saddr), "r"((uint32_t)(IO_DIM * 4))
            : "memory");
        asm volatile("cp.async.bulk.commit_group;" ::: "memory");
        // wait only until smem reads complete (writes drain independently)
        asm volatile("cp.async.bulk.wait_group.read 0;" ::: "memory");
    }
}

extern "C" void kernel_launch(void* const* d_in, const int* in_sizes, int n_in,
                              void* d_out, int out_size) {
    const float* in_ = nullptr;
    const float* sh  = nullptr;
    const float* w   = nullptr;
    for (int i = 0; i < n_in; i++) {
        if (in_sizes[i] == B_DIM * N_DIM * IO_DIM)      in_ = (const float*)d_in[i];
        else if (in_sizes[i] == B_DIM * N_DIM * 4)      sh  = (const float*)d_in[i];
        else if (in_sizes[i] == W_NUMEL)                w   = (const float*)d_in[i];
    }
    if (!in_) in_ = (const float*)d_in[0];
    if (!sh)  sh  = (const float*)d_in[1];
    if (!w)   w   = (const float*)d_in[2];

    dim3 gridA(N_DIM / 4, B_DIM);
    ftp_precompute4<<<gridA, 272>>>(in_, w);

    dim3 gridB(N_DIM, B_DIM, 4);
    ftp_fanout_tma<<<gridB, 272>>>((const float4*)sh, (float*)d_out);
}

// round 15
// speedup vs baseline: 1.1850x; 1.1850x over previous
#include <cuda_runtime.h>

// FasterTensorProduct, factored form:
//   out[b,n1,n2,o] = sum_{s=0..3} sh[b,n1,s] * P[b,n2,s,o]
// where P[b,n2,s,:] = y(x_{b,n2}, e_s) is the bilinear map on the 4 sh basis
// vectors.
//
// Kernel A (ftp_precompute2): 256 blocks x 272 threads; each block computes P
// for 2 consecutive n2 rows with 2x weight-load reuse. (vs R11's 128-block/4-row:
// same chip-wide LDG-issue budget halving, but 2x the warps/SM and no idle SMs.)
// Kernel B (ftp_fanout): proven 13.5us fan-out shape, P loads hoisted above
// the barrier. B sits at the L2 write-path cap (~46% LTS for 3 rounds running);
// this round recovers the A+gap tax instead.
//
// Dims: M0E=64, M1O=32, M1E=32, M0O=16, IN_DIM=OUT_DIM=272, B=4, N=128.
// Weights (flat, row-major, each block scaled by 1/sqrt(rows)):
//   W0e at 0     : (96,64)
//   W1o at 6144  : (128,32)
//   W1e at 10240 : (80,32)
//   W0o at 12800 : (48,16)

#define B_DIM 4
#define N_DIM 128
#define IO_DIM 272
#define W_NUMEL 13568

__device__ float4 g_Pbuf[B_DIM * N_DIM * IO_DIM];   // [b][n2][o] -> (P_s0..P_s3)

// ---------------------------------------------------------------------------
// Kernel A: compute P, 2 rows per block with 2x weight-load reuse
// grid = (64, 4), block = 272
// ---------------------------------------------------------------------------
__global__ __launch_bounds__(272) void ftp_precompute2(
    const float* __restrict__ in_, const float* __restrict__ w)
{
    __shared__ float xs[2 * IO_DIM];   // xs[r*272 + k]

    const int tid    = threadIdx.x;
    const int n2base = blockIdx.x * 2;
    const int b      = blockIdx.y;

    // 2 consecutive input rows are contiguous: 544 floats = 272 float2
    {
        const float2* src = reinterpret_cast<const float2*>(
            in_ + (size_t)(b * N_DIM + n2base) * IO_DIM);
        reinterpret_cast<float2*>(xs)[tid] = src[tid];
    }
    __syncthreads();

    const float inv2 = 0.7071067811865476f;   // 1/sqrt(2)
    const float inv3 = 0.5773502691896258f;   // 1/sqrt(3)

    float p0[2], p1[2], p2[2], p3[2];
    const int o = tid;

    if (o < 64) {
        // y0e: out0e = [x0e*sh0, (x1o . sh1)/sqrt3], W0e (96,64), 1/sqrt(96)
        const float s = 0.10206207261596575f;
        float a0[2] = {0.f,0.f};
        float a1[2] = {0.f,0.f};
        float a2[2] = {0.f,0.f};
        float a3[2] = {0.f,0.f};
        #pragma unroll
        for (int k = 0; k < 64; k++) {
            float wv = w[k * 64 + o];
            #pragma unroll
            for (int r = 0; r < 2; r++) a0[r] += xs[r * IO_DIM + k] * wv;
        }
        #pragma unroll
        for (int m = 0; m < 32; m++) {
            float wv = w[(64 + m) * 64 + o];
            #pragma unroll
            for (int r = 0; r < 2; r++) {
                a1[r] += xs[r * IO_DIM + 64 + 3 * m + 0] * wv;
                a2[r] += xs[r * IO_DIM + 64 + 3 * m + 1] * wv;
                a3[r] += xs[r * IO_DIM + 64 + 3 * m + 2] * wv;
            }
        }
        #pragma unroll
        for (int r = 0; r < 2; r++) {
            p0[r] = a0[r] * s;
            p1[r] = a1[r] * (s * inv3);
            p2[r] = a2[r] * (s * inv3);
            p3[r] = a3[r] * (s * inv3);
        }
    } else if (o < 160) {
        // y1o: o = 64 + oo*3 + cp. W1o (128,32) at 6144, 1/sqrt(128)
        // rows: [0:64) x0e*sh1[c], [64:96) x1o*sh0, [96:128) cross(x1e,sh1)/sqrt2
        const float s  = 0.08838834764831845f;
        const int  t  = o - 64;
        const int  oo = t / 3;
        const int  cp = t - 3 * oo;
        const int  ca = (cp + 1) % 3;
        const int  cb = (cp + 2) % 3;
        const float* w1 = w + 6144;
        float A[2]  = {0.f,0.f};
        float Bc[2] = {0.f,0.f};
        float Ca[2] = {0.f,0.f};
        float Cb[2] = {0.f,0.f};
        #pragma unroll
        for (int k = 0; k < 64; k++) {
            float wv = w1[k * 32 + oo];
            #pragma unroll
            for (int r = 0; r < 2; r++) Bc[r] += xs[r * IO_DIM + k] * wv;
        }
        #pragma unroll
        for (int m = 0; m < 32; m++) {
            float wva = w1[(64 + m) * 32 + oo];
            float wvb = w1[(96 + m) * 32 + oo];
            #pragma unroll
            for (int r = 0; r < 2; r++) {
                A[r]  += xs[r * IO_DIM + 64 + 3 * m + cp] * wva;
                Ca[r] += xs[r * IO_DIM + 160 + 3 * m + cb] * wvb;  // cross(x1e,e_ca)[cp] = -x1e[cb]
                Cb[r] += xs[r * IO_DIM + 160 + 3 * m + ca] * wvb;  // cross(x1e,e_cb)[cp] = +x1e[ca]
            }
        }
        #pragma unroll
        for (int r = 0; r < 2; r++) {
            p0[r] = A[r] * s;
            float vB = Bc[r] * s;
            float vA = -Ca[r] * (s * inv2);
            float vC =  Cb[r] * (s * inv2);
            p1[r] = (cp == 0) ? vB : ((ca == 0) ? vA : vC);
            p2[r] = (cp == 1) ? vB : ((ca == 1) ? vA : vC);
            p3[r] = (cp == 2) ? vB : ((ca == 2) ? vA : vC);
        }
    } else if (o < 256) {
        // y1e: o = 160 + oo*3 + cp. W1e (80,32) at 10240, 1/sqrt(80)
        // rows: [0:32) cross(x1o,sh1)/sqrt2, [32:64) x1e*sh0, [64:80) x0o*sh1[c]
        const float s  = 0.11180339887498949f;
        const int  t  = o - 160;
        const int  oo = t / 3;
        const int  cp = t - 3 * oo;
        const int  ca = (cp + 1) % 3;
        const int  cb = (cp + 2) % 3;
        const float* w2 = w + 10240;
        float A[2]  = {0.f,0.f};
        float Bc[2] = {0.f,0.f};
        float Ca[2] = {0.f,0.f};
        float Cb[2] = {0.f,0.f};
        #pragma unroll
        for (int m = 0; m < 32; m++) {
            float wva = w2[(32 + m) * 32 + oo];
            float wvb = w2[m * 32 + oo];
            #pragma unroll
            for (int r = 0; r < 2; r++) {
                A[r]  += xs[r * IO_DIM + 160 + 3 * m + cp] * wva;
                Ca[r] += xs[r * IO_DIM + 64 + 3 * m + cb] * wvb;
                Cb[r] += xs[r * IO_DIM + 64 + 3 * m + ca] * wvb;
            }
        }
        #pragma unroll
        for (int k = 0; k < 16; k++) {
            float wv = w2[(64 + k) * 32 + oo];
            #pragma unroll
            for (int r = 0; r < 2; r++) Bc[r] += xs[r * IO_DIM + 256 + k] * wv;
        }
        #pragma unroll
        for (int r = 0; r < 2; r++) {
            p0[r] = A[r] * s;
            float vB = Bc[r] * s;
            float vA = -Ca[r] * (s * inv2);
            float vC =  Cb[r] * (s * inv2);
            p1[r] = (cp == 0) ? vB : ((ca == 0) ? vA : vC);
            p2[r] = (cp == 1) ? vB : ((ca == 1) ? vA : vC);
            p3[r] = (cp == 2) ? vB : ((ca == 2) ? vA : vC);
        }
    } else {
        // y0o: o = 256 + oy. W0o (48,16) at 12800, 1/sqrt(48)
        const float s  = 0.14433756729740645f;
        const int  oy = o - 256;
        const float* w3 = w + 12800;
        float a0[2] = {0.f,0.f};
        float a1[2] = {0.f,0.f};
        float a2[2] = {0.f,0.f};
        float a3[2] = {0.f,0.f};
        #pragma unroll
        for (int k = 0; k < 16; k++) {
            float wv = w3[(32 + k) * 16 + oy];
            #pragma unroll
            for (int r = 0; r < 2; r++) a0[r] += xs[r * IO_DIM + 256 + k] * wv;
        }
        #pragma unroll
        for (int m = 0; m < 32; m++) {
            float wv = w3[m * 16 + oy];
            #pragma unroll
            for (int r = 0; r < 2; r++) {
                a1[r] += xs[r * IO_DIM + 160 + 3 * m + 0] * wv;
                a2[r] += xs[r * IO_DIM + 160 + 3 * m + 1] * wv;
                a3[r] += xs[r * IO_DIM + 160 + 3 * m + 2] * wv;
            }
        }
        #pragma unroll
        for (int r = 0; r < 2; r++) {
            p0[r] = a0[r] * s;
            p1[r] = a1[r] * (s * inv3);
            p2[r] = a2[r] * (s * inv3);
            p3[r] = a3[r] * (s * inv3);
        }
    }

    #pragma unroll
    for (int r = 0; r < 2; r++)
        g_Pbuf[(b * N_DIM + n2base + r) * IO_DIM + o] =
            make_float4(p0[r], p1[r], p2[r], p3[r]);
}

// ---------------------------------------------------------------------------
// Kernel B: fan-out   out[b,n1,n2,:] = sh[b,n1,:] . P[b,n2,:,:]
// grid = (n2=128, b=4, half=2); block = 272 threads. Proven 13.5us shape;
// P-row LDGs hoisted above the barrier to overlap the smem wait.
// ---------------------------------------------------------------------------
__global__ __launch_bounds__(272, 7) void ftp_fanout(
    const float4* __restrict__ sh4, float4* __restrict__ outv)
{
    __shared__ float4 shs[64];

    const int tid  = threadIdx.x;
    const int n2   = blockIdx.x;
    const int b    = blockIdx.y;
    const int half = blockIdx.z;

    if (tid < 64)
        shs[tid] = sh4[b * N_DIM + half * 64 + tid];

    const int o4 = tid % 68;
    const int g  = tid / 68;

    // independent of smem -> issue before the barrier
    const float4* __restrict__ Prow = g_Pbuf + (b * N_DIM + n2) * IO_DIM + o4 * 4;
    const float4 q0 = Prow[0];
    const float4 q1 = Prow[1];
    const float4 q2 = Prow[2];
    const float4 q3 = Prow[3];

    __syncthreads();

    // output float4 index: ((b*128 + n1)*128 + n2)*68 + o4, n1 = half*64 + g + 4*i
    size_t base = ((size_t)(b * N_DIM + half * 64 + g) * N_DIM + n2) * 68 + o4;
    const size_t stride = (size_t)4 * N_DIM * 68;

    #pragma unroll
    for (int i = 0; i < 16; i++) {
        float4 s4 = shs[g + 4 * i];
        float4 r;
        r.x = q0.x * s4.x + q0.y * s4.y + q0.z * s4.z + q0.w * s4.w;
        r.y = q1.x * s4.x + q1.y * s4.y + q1.z * s4.z + q1.w * s4.w;
        r.z = q2.x * s4.x + q2.y * s4.y + q2.z * s4.z + q2.w * s4.w;
        r.w = q3.x * s4.x + q3.y * s4.y + q3.z * s4.z + q3.w * s4.w;
        outv[base + (size_t)i * stride] = r;
    }
}

extern "C" void kernel_launch(void* const* d_in, const int* in_sizes, int n_in,
                              void* d_out, int out_size) {
    const float* in_ = nullptr;
    const float* sh  = nullptr;
    const float* w   = nullptr;
    for (int i = 0; i < n_in; i++) {
        if (in_sizes[i] == B_DIM * N_DIM * IO_DIM)      in_ = (const float*)d_in[i];
        else if (in_sizes[i] == B_DIM * N_DIM * 4)      sh  = (const float*)d_in[i];
        else if (in_sizes[i] == W_NUMEL)                w   = (const float*)d_in[i];
    }
    if (!in_) in_ = (const float*)d_in[0];
    if (!sh)  sh  = (const float*)d_in[1];
    if (!w)   w   = (const float*)d_in[2];

    dim3 gridA(N_DIM / 2, B_DIM);
    ftp_precompute2<<<gridA, 272>>>(in_, w);

    dim3 gridB(N_DIM, B_DIM, 2);
    ftp_fanout<<<gridB, 272>>>((const float4*)sh, (float4*)d_out);
}